// round 17
// baseline (speedup 1.0000x reference)
#include <cuda_runtime.h>

// MLP_89498528514757 — fused recommender MLP, fp32. Round 17:
// R16 champion (ncu 8.26us) with two register/width refinements:
//  (1) w3pre prefetch moved from before BAR1 to after the layer-2 partial
//      store (before BAR2): frees 16 registers across the layer-2 FFMA2
//      loop (deeper LDG batching), LDGs overlap the barrier wait.
//  (2) combine2 packed: 256 threads x (8 LDS.64 + 8 add.f32x2 + STS.64)
//      instead of 512 x (8 LDS.32 + 8 FADD) — half the issue slots.

#define NUM_USERS 100000
#define BATCH     1024
#define ROWS      4

typedef unsigned long long u64;

__device__ __forceinline__ u64 fma2(u64 a, u64 b, u64 c) {
    u64 d;
    asm("fma.rn.f32x2 %0, %1, %2, %3;" : "=l"(d) : "l"(a), "l"(b), "l"(c));
    return d;
}
__device__ __forceinline__ u64 add2(u64 a, u64 b) {
    u64 d;
    asm("add.rn.f32x2 %0, %1, %2;" : "=l"(d) : "l"(a), "l"(b));
    return d;
}
__device__ __forceinline__ u64 pack2(float x) {
    u64 d;
    asm("mov.b64 %0, {%1, %1};" : "=l"(d) : "f"(x));
    return d;
}

__global__ __launch_bounds__(512, 2)
void mlp_fused_kernel(const int*   __restrict__ user_ids,
                      const int*   __restrict__ item_ids,
                      const float* __restrict__ W1, const float* __restrict__ b1,
                      const float* __restrict__ W2, const float* __restrict__ b2,
                      const float* __restrict__ W3, const float* __restrict__ b3,
                      const float* __restrict__ W4, const float* __restrict__ b4,
                      float*       __restrict__ out)
{
    __shared__ float4 h1t[256];                 // [k] -> rows 01|23   (4 KB)
    __shared__ union {
        float4 l2[8][128];                      // [ks][j] -> 4 rows  (16 KB)
        float4 l3[8][64];                       // [ks][j] -> 4 rows   (8 KB)
    } P;
    __shared__ float4 h2t[128];                 // [k] -> 4 rows       (2 KB)

    const int t    = threadIdx.x;               // 0..511
    const int row0 = blockIdx.x * ROWS;

    // ---------------- Layer 1: dependent gather chain, vectorized head -----
    const int4 uid4 = *reinterpret_cast<const int4*>(user_ids + row0);
    const int4 iid4 = *reinterpret_cast<const int4*>(item_ids + row0);

    const int k1 = t & 255;
    const int g  = t >> 8;                      // 0/1 -> rows {2g, 2g+1}
    const int ua = (g == 0) ? uid4.x : uid4.z;
    const int ub = (g == 0) ? uid4.y : uid4.w;
    const int ia = (g == 0) ? iid4.x : iid4.z;
    const int ib = (g == 0) ? iid4.y : iid4.w;
    const float ga = W1[ua * 256 + k1], ea = W1[(NUM_USERS + ia) * 256 + k1];
    const float gb = W1[ub * 256 + k1], eb = W1[(NUM_USERS + ib) * 256 + k1];

    // ---- overlap while the gather is in flight ----------------------------
    // layer 2: j-pair jp = t&63 -> cols {2jp, 2jp+1}; k-slice ks = t>>6 (0..7)
    const int jp = t & 63;
    const int ks = t >> 6;
    const float2* __restrict__ w2p =
        reinterpret_cast<const float2*>(W2) + (ks * 32) * 64 + jp;
    float2 w2pre[8];
    #pragma unroll
    for (int i = 0; i < 8; ++i) w2pre[i] = w2p[i * 64];   // head: 8 of 32 iters

    const float bj2 = (t < 256) ? b2[t >> 1] : 0.f;       // combine2: j = t>>1
    float w4a = 0.f, w4b = 0.f, bb4 = 0.f, b3a = 0.f, b3b = 0.f;
    if (t < 32) {
        w4a = W4[t];  w4b = W4[t + 32];
        b3a = b3[t];  b3b = b3[t + 32];
        bb4 = b4[0];
    }

    // finish layer 1: thread writes its 2 rows of h1t[k1] (8B STS)
    {
        const float bk = b1[k1];
        float2 h;
        h.x = fmaxf(ga + ea + bk, 0.f);
        h.y = fmaxf(gb + eb + bk, 0.f);
        *reinterpret_cast<float2*>(
            reinterpret_cast<float*>(&h1t[k1]) + g * 2) = h;
    }
    __syncthreads();                            // BAR 1

    // ------- Layer 2: [4x256] @ W2[256x128], 8-way K, 2 j/thread, FFMA2 ----
    {
        u64 ae01 = 0ull, ae23 = 0ull;           // col 2jp:   rows 01 | 23
        u64 ao01 = 0ull, ao23 = 0ull;           // col 2jp+1: rows 01 | 23
        #pragma unroll
        for (int kk = 0; kk < 8; ++kk) {        // weights already in regs
            const float2 w = w2pre[kk];
            const ulonglong2 v =
                *reinterpret_cast<const ulonglong2*>(&h1t[ks * 32 + kk]);
            const u64 wx = pack2(w.x), wy = pack2(w.y);
            ae01 = fma2(v.x, wx, ae01);  ae23 = fma2(v.y, wx, ae23);
            ao01 = fma2(v.x, wy, ao01);  ao23 = fma2(v.y, wy, ao23);
        }
        #pragma unroll
        for (int kk = 8; kk < 32; ++kk) {
            const float2 w = w2p[kk * 64];      // LDG.64, warp spans 256B
            const ulonglong2 v =
                *reinterpret_cast<const ulonglong2*>(&h1t[ks * 32 + kk]);
            const u64 wx = pack2(w.x), wy = pack2(w.y);
            ae01 = fma2(v.x, wx, ae01);  ae23 = fma2(v.y, wx, ae23);
            ao01 = fma2(v.x, wy, ao01);  ao23 = fma2(v.y, wy, ao23);
        }
        ulonglong2 se; se.x = ae01; se.y = ae23;
        ulonglong2 so; so.x = ao01; so.y = ao23;
        *reinterpret_cast<ulonglong2*>(&P.l2[ks][jp * 2 + 0]) = se;  // STS.128
        *reinterpret_cast<ulonglong2*>(&P.l2[ks][jp * 2 + 1]) = so;
    }

    // ---- layer-3 weight prefetch HERE (accumulators dead, regs free;
    //      LDGs overlap the barrier wait) ------------------------------------
    const int j3  = t & 63;
    const int k83 = t >> 6;
    float w3pre[16];
    {
        const float* __restrict__ w3p = W3 + (k83 * 16) * 64 + j3;
        #pragma unroll
        for (int i = 0; i < 16; ++i) w3pre[i] = w3p[i * 64];
    }
    __syncthreads();                            // BAR 2

    // combine layer-2 partials (packed): 256 threads, (j = t>>1, rp = t&1)
    if (t < 256) {
        const int j = t >> 1, rp = t & 1;       // rp: row-pair 01 or 23
        u64 s = pack2(bj2);
        #pragma unroll
        for (int q = 0; q < 8; ++q)
            s = add2(s, reinterpret_cast<const u64*>(&P.l2[q][j])[rp]);
        // packed ReLU: max each half with 0 via fmaxf on unpacked halves
        float lo = __uint_as_float((unsigned)(s & 0xffffffffull));
        float hi = __uint_as_float((unsigned)(s >> 32));
        float2 hv; hv.x = fmaxf(lo, 0.f); hv.y = fmaxf(hi, 0.f);
        reinterpret_cast<float2*>(&h2t[j])[rp] = hv;
    }
    __syncthreads();                            // BAR 3

    // ------- Layer 3: [4x128] @ W3[128x64], 8-way split-K, FFMA2 -----------
    {
        u64 a01 = 0ull, a23 = 0ull;
        #pragma unroll
        for (int kk = 0; kk < 16; ++kk) {
            const u64 ww = pack2(w3pre[kk]);
            const ulonglong2 v =
                *reinterpret_cast<const ulonglong2*>(&h2t[k83 * 16 + kk]);
            a01 = fma2(v.x, ww, a01);
            a23 = fma2(v.y, ww, a23);
        }
        ulonglong2 sv; sv.x = a01; sv.y = a23;
        *reinterpret_cast<ulonglong2*>(&P.l3[k83][j3]) = sv;
    }
    __syncthreads();                            // BAR 4

    // ------- fused combine3 + Layer 4 (warp 0 only) ------------------------
    if (t < 32) {
        float4 acc = make_float4(0.f, 0.f, 0.f, 0.f);
        #pragma unroll
        for (int jj = 0; jj < 2; ++jj) {
            const int   j  = t + jj * 32;
            const float bj = jj ? b3b : b3a;
            const float w4 = jj ? w4b : w4a;
            float4 s = make_float4(bj, bj, bj, bj);
            #pragma unroll
            for (int q = 0; q < 8; ++q) {       // LDS.128, conflict-free
                const float4 p = P.l3[q][j];
                s.x += p.x; s.y += p.y; s.z += p.z; s.w += p.w;
            }
            acc.x = fmaf(fmaxf(s.x, 0.f), w4, acc.x);
            acc.y = fmaf(fmaxf(s.y, 0.f), w4, acc.y);
            acc.z = fmaf(fmaxf(s.z, 0.f), w4, acc.z);
            acc.w = fmaf(fmaxf(s.w, 0.f), w4, acc.w);
        }
        #pragma unroll
        for (int off = 16; off > 0; off >>= 1) {
            acc.x += __shfl_down_sync(0xffffffffu, acc.x, off);
            acc.y += __shfl_down_sync(0xffffffffu, acc.y, off);
            acc.z += __shfl_down_sync(0xffffffffu, acc.z, off);
            acc.w += __shfl_down_sync(0xffffffffu, acc.w, off);
        }
        if (t == 0) {
            out[row0 + 0] = acc.x + bb4;
            out[row0 + 1] = acc.y + bb4;
            out[row0 + 2] = acc.z + bb4;
            out[row0 + 3] = acc.w + bb4;
        }
    }
}

extern "C" void kernel_launch(void* const* d_in, const int* in_sizes, int n_in,
                              void* d_out, int out_size)
{
    const int*   user_ids = (const int*)  d_in[0];
    const int*   item_ids = (const int*)  d_in[1];
    const float* W1       = (const float*)d_in[2];
    const float* b1       = (const float*)d_in[3];
    const float* W2       = (const float*)d_in[4];
    const float* b2       = (const float*)d_in[5];
    const float* W3       = (const float*)d_in[6];
    const float* b3       = (const float*)d_in[7];
    const float* W4       = (const float*)d_in[8];
    const float* b4       = (const float*)d_in[9];
    float*       out      = (float*)d_out;

    mlp_fused_kernel<<<BATCH / ROWS, 512>>>(user_ids, item_ids,
                                            W1, b1, W2, b2, W3, b3, W4, b4, out);
}